// round 3
// baseline (speedup 1.0000x reference)
#include <cuda_runtime.h>
#include <cstdint>

// Problem constants (fixed shapes)
#define B_ROWS   131072
#define IN_DIM   128
#define OUT_DIM  32
#define NBASIS   8
#define NFEAT    9            // 1 silu + 8 basis
#define KDIM     (IN_DIM * NFEAT)   // 1152

// Folded weight matrix W[K=1152][32] and bias[32]
__device__ __align__(16) float g_W[KDIM * OUT_DIM];
__device__ __align__(16) float g_bias[OUT_DIM];

// ---------------- packed f32x2 helpers (sm_103a) ----------------
__device__ __forceinline__ unsigned long long pk2(float v) {
    unsigned long long r;
    asm("mov.b64 %0, {%1, %1};" : "=l"(r) : "f"(v));
    return r;
}
__device__ __forceinline__ unsigned long long fma2(unsigned long long a,
                                                   unsigned long long b,
                                                   unsigned long long c) {
    unsigned long long d;
    asm("fma.rn.f32x2 %0, %1, %2, %3;" : "=l"(d) : "l"(a), "l"(b), "l"(c));
    return d;
}
__device__ __forceinline__ unsigned long long add2(unsigned long long a,
                                                   unsigned long long b) {
    unsigned long long d;
    asm("add.rn.f32x2 %0, %1, %2;" : "=l"(d) : "l"(a), "l"(b));
    return d;
}

// ---------------- spline constants ----------------
// grid = linspace(-1, 1, 12); centers = grid[3..10]; spacing = 2/5 + 1e-6
#define KAN_C0     (-1.0f + 6.0f / 11.0f)       // first center = -5/11
#define KAN_DSTEP  (2.0f / 11.0f)               // knot step
#define KAN_SPACE  (0.4f + 1e-6f)
#define KAN_INVS   (1.0f / KAN_SPACE)

// features: f[0] = silu(x), f[1..8] = exp(-0.5*((x-c_k)/s)^2)
__device__ __forceinline__ void kan_feats(float x, float f[NFEAT]) {
    float e = __expf(-x);
    f[0] = __fdividef(x, 1.0f + e);
    float z = (x - KAN_C0) * KAN_INVS;
    const float zs = KAN_DSTEP * KAN_INVS;
#pragma unroll
    for (int k = 0; k < NBASIS; ++k) {
        f[1 + k] = __expf(-0.5f * z * z);
        z -= zs;
    }
}

// ---------------- weight folding ----------------
// W[(i*9+0)][j]   = ew[i][j] * base_weight[i][j]
// W[(i*9+1+k)][j] = ew[i][j] * coeff[i][j][k]
__global__ void kan_prep(const float* __restrict__ coeff,
                         const float* __restrict__ bw,
                         const float* __restrict__ ew) {
    int t = blockIdx.x * blockDim.x + threadIdx.x;
    if (t >= IN_DIM * OUT_DIM) return;
    int i = t >> 5;          // input index
    int j = t & 31;          // output index
    float e = ew[t];
    g_W[(i * NFEAT) * OUT_DIM + j] = e * bw[t];
#pragma unroll
    for (int k = 0; k < NBASIS; ++k)
        g_W[(i * NFEAT + 1 + k) * OUT_DIM + j] = e * coeff[t * NBASIS + k];
}

__global__ void kan_prep_bias(const float* __restrict__ bb,
                              const float* __restrict__ ew) {
    int j = threadIdx.x;
    if (j < OUT_DIM) {
        float s = 0.0f;
        for (int i = 0; i < IN_DIM; ++i)
            s += ew[i * OUT_DIM + j] * bb[i * OUT_DIM + j];
        g_bias[j] = s;
    }
}

// ---------------- main kernel ----------------
// 64 threads/block, 2 rows/thread -> 128 rows/block, grid = 1024 blocks.
// Each thread: 32 output accumulators as 16 packed f32x2.
#define TPB        64
#define ROWS_BLK   128
#define CHUNK      16

__global__ __launch_bounds__(TPB)
void kan_main(const float* __restrict__ x, float* __restrict__ out) {
    __shared__ float xs[ROWS_BLK][CHUNK + 1];   // +1 pad: conflict-free column reads

    const int tid = threadIdx.x;
    const long long base = (long long)blockIdx.x * ROWS_BLK;
    const float* __restrict__ xblk = x + base * IN_DIM;

    unsigned long long acc0[16], acc1[16];
#pragma unroll
    for (int h = 0; h < 16; ++h) { acc0[h] = 0ull; acc1[h] = 0ull; }

    for (int i0 = 0; i0 < IN_DIM; i0 += CHUNK) {
        __syncthreads();
        // stage x[128 rows][16 cols] (coalesced 64B-contiguous per row)
#pragma unroll
        for (int k = 0; k < (ROWS_BLK * CHUNK) / TPB; ++k) {
            int e = tid + k * TPB;
            int r = e >> 4, c = e & 15;
            xs[r][c] = xblk[r * IN_DIM + i0 + c];
        }
        __syncthreads();

#pragma unroll 1
        for (int ii = 0; ii < CHUNK; ++ii) {
            const int i = i0 + ii;
            float fa[NFEAT], fb[NFEAT];
            kan_feats(xs[tid][ii], fa);
            kan_feats(xs[tid + TPB][ii], fb);

            const ulonglong2* __restrict__ wp =
                (const ulonglong2*)(g_W + i * (NFEAT * OUT_DIM));
#pragma unroll
            for (int f = 0; f < NFEAT; ++f) {
                unsigned long long pa = pk2(fa[f]);
                unsigned long long pb = pk2(fb[f]);
#pragma unroll
                for (int h = 0; h < 8; ++h) {
                    ulonglong2 w = wp[f * 8 + h];       // W[i*9+f][4h .. 4h+3]
                    acc0[2 * h]     = fma2(pa, w.x, acc0[2 * h]);
                    acc0[2 * h + 1] = fma2(pa, w.y, acc0[2 * h + 1]);
                    acc1[2 * h]     = fma2(pb, w.x, acc1[2 * h]);
                    acc1[2 * h + 1] = fma2(pb, w.y, acc1[2 * h + 1]);
                }
            }
        }
    }

    // add bias, store 32 floats per row as 8x STG.128
    const unsigned long long* bp = (const unsigned long long*)g_bias;
    ulonglong2* o0 = (ulonglong2*)(out + (base + tid) * OUT_DIM);
    ulonglong2* o1 = (ulonglong2*)(out + (base + TPB + tid) * OUT_DIM);
#pragma unroll
    for (int h = 0; h < 8; ++h) {
        unsigned long long b0 = bp[2 * h], b1 = bp[2 * h + 1];
        ulonglong2 v0, v1;
        v0.x = add2(acc0[2 * h], b0);
        v0.y = add2(acc0[2 * h + 1], b1);
        v1.x = add2(acc1[2 * h], b0);
        v1.y = add2(acc1[2 * h + 1], b1);
        o0[h] = v0;
        o1[h] = v1;
    }
}

// ---------------- launch ----------------
extern "C" void kernel_launch(void* const* d_in, const int* in_sizes, int n_in,
                              void* d_out, int out_size) {
    (void)in_sizes; (void)n_in; (void)out_size;
    const float* x     = (const float*)d_in[0];
    const float* coeff = (const float*)d_in[1];
    const float* bw    = (const float*)d_in[2];
    const float* bb    = (const float*)d_in[3];
    const float* ew    = (const float*)d_in[4];
    float* out = (float*)d_out;

    kan_prep<<<(IN_DIM * OUT_DIM + 255) / 256, 256>>>(coeff, bw, ew);
    kan_prep_bias<<<1, 32>>>(bb, ew);
    kan_main<<<B_ROWS / ROWS_BLK, TPB>>>(x, out);
}

// round 6
// speedup vs baseline: 3.1793x; 3.1793x over previous
#include <cuda_runtime.h>
#include <cuda_bf16.h>
#include <cstdint>

#define IN_DIM   128
#define OUT_DIM  32
#define NCHUNK   32            // 4 inputs per chunk
#define WCH      10240         // W chunk: 128 k-rows * 80B (64B data + 16B pad)
#define ROWPAD   272           // A tile row pitch: 256B data + 16B pad
#define TPB      128
#define NCTA     1024          // 131072 rows / 128

// smem layout (bytes)
#define OFF_XS   0             // x stage: 128 rows * 144B (32 floats + pad)
#define OFF_A    18432         // A tile: 128 * 272
#define OFF_W    53248         // W ring: 2 * 10240
#define SMEM_TOTAL 73728

// spline constants: centers start -5/11, step 2/11, spacing 0.4+1e-6
#define KAN_C0   (-5.0f / 11.0f)
#define KAN_IS   (1.0f / (0.4f + 1e-6f))
#define KAN_D1   ((2.0f / 11.0f) * KAN_IS)

__device__ __align__(16) uint8_t g_W[NCHUNK * WCH];   // pre-folded, split, padded B image
__device__ __align__(16) float   g_bias[OUT_DIM];

// ---------------- helpers ----------------
__device__ __forceinline__ uint32_t smem_u32(const void* p) {
    uint32_t a;
    asm("{ .reg .u64 t; cvta.to.shared.u64 t, %1; cvt.u32.u64 %0, t; }" : "=r"(a) : "l"(p));
    return a;
}
__device__ __forceinline__ void cp16(uint32_t sdst, const void* gsrc) {
    asm volatile("cp.async.ca.shared.global [%0], [%1], 16;"
        :: "r"(sdst), "l"(__cvta_generic_to_global(gsrc)));
}
#define CP_COMMIT() asm volatile("cp.async.commit_group;" ::: "memory")
#define CP_WAIT1()  asm volatile("cp.async.wait_group 1;" ::: "memory")

__device__ __forceinline__ void ldsm4(uint32_t* r, uint32_t a) {
    asm volatile("ldmatrix.sync.aligned.m8n8.x4.shared.b16 {%0,%1,%2,%3}, [%4];"
        : "=r"(r[0]), "=r"(r[1]), "=r"(r[2]), "=r"(r[3]) : "r"(a));
}
__device__ __forceinline__ void ldsm4t(uint32_t* r, uint32_t a) {
    asm volatile("ldmatrix.sync.aligned.m8n8.x4.trans.shared.b16 {%0,%1,%2,%3}, [%4];"
        : "=r"(r[0]), "=r"(r[1]), "=r"(r[2]), "=r"(r[3]) : "r"(a));
}
__device__ __forceinline__ void mma16816(float* d, const uint32_t* a, const uint32_t* b) {
    asm volatile("mma.sync.aligned.m16n8k16.row.col.f32.bf16.bf16.f32 "
        "{%0,%1,%2,%3}, {%4,%5,%6,%7}, {%8,%9}, {%0,%1,%2,%3};"
        : "+f"(d[0]), "+f"(d[1]), "+f"(d[2]), "+f"(d[3])
        : "r"(a[0]), "r"(a[1]), "r"(a[2]), "r"(a[3]), "r"(b[0]), "r"(b[1]));
}
__device__ __forceinline__ uint32_t pkbf(float lo, float hi) {   // low half = lo
    uint32_t r;
    asm("cvt.rn.bf16x2.f32 %0, %1, %2;" : "=r"(r) : "f"(hi), "f"(lo));
    return r;
}
__device__ __forceinline__ float bfres(float v) {
    return v - __bfloat162float(__float2bfloat16_rn(v));
}

// ---------------- prep: fold weights, bf16 hi/lo split, pad rows ----------------
// k layout per input (32 rows): [0-8]=Wh  [9-17]=Wh  [18-26]=Wl  [27-31]=0
// (paired with A slots:         [0-8]=Fh  [9-17]=Fl  [18-26]=Fh  [27-31]=0)
__global__ void kan_prep(const float* __restrict__ coeff, const float* __restrict__ bw,
                         const float* __restrict__ bb, const float* __restrict__ ew) {
    int t = blockIdx.x * 256 + threadIdx.x;
    if (t < IN_DIM * OUT_DIM) {
        int i = t >> 5, j = t & 31;
        float e = ew[t];
        float w[9];
        w[0] = e * bw[t];
#pragma unroll
        for (int k = 0; k < 8; ++k) w[1 + k] = e * coeff[t * 8 + k];
        uint8_t* base = g_W + (i >> 2) * WCH + (i & 3) * 32 * 80 + j * 2;
#pragma unroll
        for (int f = 0; f < 9; ++f) {
            __nv_bfloat16 wh = __float2bfloat16_rn(w[f]);
            __nv_bfloat16 wl = __float2bfloat16_rn(w[f] - __bfloat162float(wh));
            *(__nv_bfloat16*)(base + f * 80)        = wh;
            *(__nv_bfloat16*)(base + (9 + f) * 80)  = wh;
            *(__nv_bfloat16*)(base + (18 + f) * 80) = wl;
        }
#pragma unroll
        for (int p = 27; p < 32; ++p)        // zero pad rows
            *(__nv_bfloat16*)(base + p * 80) = __float2bfloat16_rn(0.0f);
    }
    if (blockIdx.x == 0 && threadIdx.x < OUT_DIM) {
        int j = threadIdx.x;
        float s = 0.0f;
        for (int i = 0; i < IN_DIM; ++i) s += ew[i * OUT_DIM + j] * bb[i * OUT_DIM + j];
        g_bias[j] = s;
    }
}

// ---------------- main: features -> smem A tile -> ldmatrix -> mma.sync ----------------
extern __shared__ uint8_t sm[];

__global__ __launch_bounds__(TPB)
void kan_main(const float* __restrict__ x, float* __restrict__ out) {
    const int tid  = threadIdx.x;
    const int wid  = tid >> 5;
    const int lane = tid & 31;
    const int g    = lane >> 2;
    const int tig  = lane & 3;
    const uint32_t sb = smem_u32(sm);
    const uint32_t a_b = sb + OFF_A, w_b = sb + OFF_W;

    const int rowBase = blockIdx.x * TPB;
    const float* __restrict__ xblk = x + (size_t)rowBase * IN_DIM;

    float2 bias[4];
#pragma unroll
    for (int j = 0; j < 4; ++j) bias[j] = *(const float2*)(g_bias + j * 8 + tig * 2);

    float acc[2][4][4];
#pragma unroll
    for (int t = 0; t < 2; ++t)
#pragma unroll
        for (int j = 0; j < 4; ++j)
#pragma unroll
            for (int r = 0; r < 4; ++r) acc[t][j][r] = 0.0f;

    const float QC = __expf(-KAN_D1 * KAN_D1);
    const float MB = -0.5f * KAN_D1 * KAN_D1;

    // prologue: W chunk 0 -> buf0  (10240B = 640 x 16B, 5 per thread)
#pragma unroll
    for (int k = 0; k < 5; ++k)
        cp16(w_b + (uint32_t)(tid + k * 128) * 16, g_W + (tid + k * 128) * 16);
    CP_COMMIT();

#pragma unroll 1
    for (int c = 0; c < NCHUNK; ++c) {
        __syncthreads();   // all warps done reading buf((c+1)&1) [iter c-1] and A tile

        // distance-1 prefetch: chunk c+1 into the buffer freed at iter c-1
        if (c + 1 < NCHUNK) {
            const uint8_t* src = g_W + (size_t)(c + 1) * WCH;
            uint32_t dst = w_b + (uint32_t)((c + 1) & 1) * WCH;
#pragma unroll
            for (int k = 0; k < 5; ++k)
                cp16(dst + (uint32_t)(tid + k * 128) * 16, src + (tid + k * 128) * 16);
        }
        CP_COMMIT();       // commit every iter so group counting stays uniform

        // stage x tile (128 rows x 32 cols) every 8 chunks, coalesced
        if ((c & 7) == 0) {
            const int p = c >> 3;
#pragma unroll
            for (int i = 0; i < 8; ++i) {
                int n = tid + i * 128;         // 1024 float4s
                int row = n >> 3, c4 = n & 7;
                float4 v = *(const float4*)(xblk + row * IN_DIM + p * 32 + c4 * 4);
                *(float4*)(sm + OFF_XS + row * 144 + c4 * 16) = v;
            }
            __syncthreads();
        }

        // features for this thread's row (4 inputs), pack, STS into A tile
        float4 xv = *(const float4*)(sm + OFF_XS + tid * 144 + (c & 7) * 16);
        const float xin[4] = {xv.x, xv.y, xv.z, xv.w};
#pragma unroll
        for (int q = 0; q < 4; ++q) {
            float xq = xin[q];
            float f[9];
            float e = __expf(-xq);
            f[0] = __fdividef(xq, 1.0f + e);                 // silu
            float z0 = (xq - KAN_C0) * KAN_IS;
            float b = __expf(-0.5f * z0 * z0);
            float m = __expf(fmaf(z0, KAN_D1, MB));
            f[1] = b;
#pragma unroll
            for (int k = 2; k <= 8; ++k) { b *= m; m *= QC; f[k] = b; }
            float l[9];
#pragma unroll
            for (int k = 0; k < 9; ++k) l[k] = bfres(f[k]);

            uint32_t u[16];
            u[0]  = pkbf(f[0], f[1]); u[1]  = pkbf(f[2], f[3]);
            u[2]  = pkbf(f[4], f[5]); u[3]  = pkbf(f[6], f[7]);
            u[4]  = pkbf(f[8], l[0]); u[5]  = pkbf(l[1], l[2]);
            u[6]  = pkbf(l[3], l[4]); u[7]  = pkbf(l[5], l[6]);
            u[8]  = pkbf(l[7], l[8]);
            u[9]  = u[0]; u[10] = u[1]; u[11] = u[2]; u[12] = u[3];
            u[13] = pkbf(f[8], 0.0f); u[14] = 0u; u[15] = 0u;

            uint4* dst = (uint4*)(sm + OFF_A + tid * ROWPAD + q * 64);
            dst[0] = make_uint4(u[0],  u[1],  u[2],  u[3]);
            dst[1] = make_uint4(u[4],  u[5],  u[6],  u[7]);
            dst[2] = make_uint4(u[8],  u[9],  u[10], u[11]);
            dst[3] = make_uint4(u[12], u[13], u[14], u[15]);
        }

        CP_WAIT1();        // retire chunk c's group (<=1 pending: the c+1 group)
        __syncthreads();   // A tile + W chunk c visible to every warp

        const uint32_t wbuf = w_b + (uint32_t)(c & 1) * WCH;
        const uint32_t aW = a_b + (uint32_t)(wid * 32) * ROWPAD;
#pragma unroll
        for (int s = 0; s < 8; ++s) {
            uint32_t a0[4], a1[4], b01[4], b23[4];
            uint32_t arow = aW + (uint32_t)(lane & 15) * ROWPAD + s * 32 + (lane >> 4) * 16;
            ldsm4(a0, arow);
            ldsm4(a1, arow + 16 * ROWPAD);
            uint32_t brow = wbuf + (uint32_t)(16 * s + (lane & 15)) * 80 + (lane >> 4) * 16;
            ldsm4t(b01, brow);                 // n-tiles 0,1
            ldsm4t(b23, brow + 32);            // n-tiles 2,3
            mma16816(acc[0][0], a0, b01 + 0); mma16816(acc[0][1], a0, b01 + 2);
            mma16816(acc[0][2], a0, b23 + 0); mma16816(acc[0][3], a0, b23 + 2);
            mma16816(acc[1][0], a1, b01 + 0); mma16816(acc[1][1], a1, b01 + 2);
            mma16816(acc[1][2], a1, b23 + 0); mma16816(acc[1][3], a1, b23 + 2);
        }
    }

    // epilogue: bias + store (D frag: d0,d1 -> row g; d2,d3 -> row g+8)
#pragma unroll
    for (int t = 0; t < 2; ++t) {
        int r0 = rowBase + wid * 32 + t * 16 + g;
#pragma unroll
        for (int j = 0; j < 4; ++j) {
            float2 v0 = make_float2(acc[t][j][0] + bias[j].x, acc[t][j][1] + bias[j].y);
            float2 v1 = make_float2(acc[t][j][2] + bias[j].x, acc[t][j][3] + bias[j].y);
            *(float2*)(out + (size_t)r0 * OUT_DIM + j * 8 + tig * 2)       = v0;
            *(float2*)(out + (size_t)(r0 + 8) * OUT_DIM + j * 8 + tig * 2) = v1;
        }
    }
}

// ---------------- launch ----------------
extern "C" void kernel_launch(void* const* d_in, const int* in_sizes, int n_in,
                              void* d_out, int out_size) {
    (void)in_sizes; (void)n_in; (void)out_size;
    const float* x     = (const float*)d_in[0];
    const float* coeff = (const float*)d_in[1];
    const float* bw    = (const float*)d_in[2];
    const float* bb    = (const float*)d_in[3];
    const float* ew    = (const float*)d_in[4];
    float* out = (float*)d_out;

    cudaFuncSetAttribute(kan_main, cudaFuncAttributeMaxDynamicSharedMemorySize, SMEM_TOTAL);

    kan_prep<<<16, 256>>>(coeff, bw, bb, ew);
    kan_main<<<NCTA, TPB, SMEM_TOTAL>>>(x, out);
}

// round 8
// speedup vs baseline: 6.2456x; 1.9644x over previous
#include <cuda_runtime.h>
#include <cuda_bf16.h>
#include <cstdint>

#define IN_DIM   128
#define OUT_DIM  32
#define NCHUNK   32            // 4 inputs per chunk
#define SLOTS    28            // per input: [0-8]=Fh [9-17]=Fl [18-26]=Fh [27]=0
#define KSTEPS   7             // 4*28/16
#define WCH      8960          // W chunk: 112 k-rows * 80B (64B data + 16B pad)
#define ROWPAD   240           // A tile row pitch: 224B data + 16B pad
#define TPB      128
#define NCTA     1024          // 131072 rows / 128

// smem layout (bytes): A tile then W ring
#define OFF_A    0             // 128 * 240 = 30720
#define OFF_W    30720         // 2 * 8960 = 17920
#define SMEM_TOTAL 48640

// spline constants: centers start -5/11, step 2/11, spacing 0.4+1e-6
#define KAN_C0   (-5.0f / 11.0f)
#define KAN_IS   (1.0f / (0.4f + 1e-6f))
#define KAN_D1   ((2.0f / 11.0f) * KAN_IS)

__device__ __align__(16) uint8_t g_W[NCHUNK * WCH];   // pre-folded, split, padded B image
__device__ __align__(16) float   g_bias[OUT_DIM];

// ---------------- helpers ----------------
__device__ __forceinline__ uint32_t smem_u32(const void* p) {
    uint32_t a;
    asm("{ .reg .u64 t; cvta.to.shared.u64 t, %1; cvt.u32.u64 %0, t; }" : "=r"(a) : "l"(p));
    return a;
}
__device__ __forceinline__ void cp16(uint32_t sdst, const void* gsrc) {
    asm volatile("cp.async.ca.shared.global [%0], [%1], 16;"
        :: "r"(sdst), "l"(__cvta_generic_to_global(gsrc)));
}
#define CP_COMMIT() asm volatile("cp.async.commit_group;" ::: "memory")
#define CP_WAIT0()  asm volatile("cp.async.wait_group 0;" ::: "memory")

__device__ __forceinline__ void ldsm4(uint32_t* r, uint32_t a) {
    asm volatile("ldmatrix.sync.aligned.m8n8.x4.shared.b16 {%0,%1,%2,%3}, [%4];"
        : "=r"(r[0]), "=r"(r[1]), "=r"(r[2]), "=r"(r[3]) : "r"(a));
}
__device__ __forceinline__ void ldsm4t(uint32_t* r, uint32_t a) {
    asm volatile("ldmatrix.sync.aligned.m8n8.x4.trans.shared.b16 {%0,%1,%2,%3}, [%4];"
        : "=r"(r[0]), "=r"(r[1]), "=r"(r[2]), "=r"(r[3]) : "r"(a));
}
__device__ __forceinline__ void mma16816(float* d, const uint32_t* a, const uint32_t* b) {
    asm volatile("mma.sync.aligned.m16n8k16.row.col.f32.bf16.bf16.f32 "
        "{%0,%1,%2,%3}, {%4,%5,%6,%7}, {%8,%9}, {%0,%1,%2,%3};"
        : "+f"(d[0]), "+f"(d[1]), "+f"(d[2]), "+f"(d[3])
        : "r"(a[0]), "r"(a[1]), "r"(a[2]), "r"(a[3]), "r"(b[0]), "r"(b[1]));
}
__device__ __forceinline__ uint32_t pkbf(float lo, float hi) {   // low half = lo
    uint32_t r;
    asm("cvt.rn.bf16x2.f32 %0, %1, %2;" : "=r"(r) : "f"(hi), "f"(lo));
    return r;
}
__device__ __forceinline__ float bfres(float v) {
    return v - __bfloat162float(__float2bfloat16_rn(v));
}

// ---------------- prep: fold weights, bf16 hi/lo split, 28-row groups ----------------
// per input (28 rows): [0-8]=Wh  [9-17]=Wh  [18-26]=Wl  [27]=0
__global__ void kan_prep(const float* __restrict__ coeff, const float* __restrict__ bw,
                         const float* __restrict__ bb, const float* __restrict__ ew) {
    int t = blockIdx.x * 256 + threadIdx.x;
    if (t < IN_DIM * OUT_DIM) {
        int i = t >> 5, j = t & 31;
        float e = ew[t];
        float w[9];
        w[0] = e * bw[t];
#pragma unroll
        for (int k = 0; k < 8; ++k) w[1 + k] = e * coeff[t * 8 + k];
        uint8_t* base = g_W + (i >> 2) * WCH + (i & 3) * SLOTS * 80 + j * 2;
#pragma unroll
        for (int f = 0; f < 9; ++f) {
            __nv_bfloat16 wh = __float2bfloat16_rn(w[f]);
            __nv_bfloat16 wl = __float2bfloat16_rn(w[f] - __bfloat162float(wh));
            *(__nv_bfloat16*)(base + f * 80)        = wh;
            *(__nv_bfloat16*)(base + (9 + f) * 80)  = wh;
            *(__nv_bfloat16*)(base + (18 + f) * 80) = wl;
        }
        *(__nv_bfloat16*)(base + 27 * 80) = __float2bfloat16_rn(0.0f);
    }
    if (blockIdx.x == 0 && threadIdx.x < OUT_DIM) {
        int j = threadIdx.x;
        float s = 0.0f;
        for (int i = 0; i < IN_DIM; ++i) s += ew[i * OUT_DIM + j] * bb[i * OUT_DIM + j];
        g_bias[j] = s;
    }
}

// ---------------- main ----------------
extern __shared__ uint8_t sm[];

// features for one x -> 14 packed words (28 bf16 slots)
__device__ __forceinline__ void feat_words(float xq, uint32_t* wp) {
    const float QC = __expf(-KAN_D1 * KAN_D1);
    const float MB = -0.5f * KAN_D1 * KAN_D1;
    float f[9];
    float e = __expf(-xq);
    f[0] = __fdividef(xq, 1.0f + e);                 // silu
    float z0 = (xq - KAN_C0) * KAN_IS;
    float b = __expf(-0.5f * z0 * z0);
    float m = __expf(fmaf(z0, KAN_D1, MB));
    f[1] = b;
#pragma unroll
    for (int k = 2; k <= 8; ++k) { b *= m; m *= QC; f[k] = b; }
    float l[9];
#pragma unroll
    for (int k = 0; k < 9; ++k) l[k] = bfres(f[k]);
    wp[0]  = pkbf(f[0], f[1]); wp[1]  = pkbf(f[2], f[3]);
    wp[2]  = pkbf(f[4], f[5]); wp[3]  = pkbf(f[6], f[7]);
    wp[4]  = pkbf(f[8], l[0]); wp[5]  = pkbf(l[1], l[2]);
    wp[6]  = pkbf(l[3], l[4]); wp[7]  = pkbf(l[5], l[6]);
    wp[8]  = pkbf(l[7], l[8]);
    wp[9]  = wp[0]; wp[10] = wp[1]; wp[11] = wp[2]; wp[12] = wp[3];
    wp[13] = pkbf(f[8], 0.0f);
}

__global__ __launch_bounds__(TPB, 4)
void kan_main(const float* __restrict__ x, float* __restrict__ out) {
    const int tid  = threadIdx.x;
    const int wid  = tid >> 5;
    const int lane = tid & 31;
    const int g    = lane >> 2;
    const int tig  = lane & 3;
    const uint32_t sb  = smem_u32(sm);
    const uint32_t a_b = sb + OFF_A, w_b = sb + OFF_W;

    const int rowBase = blockIdx.x * TPB;
    const float* __restrict__ xrow = x + (size_t)(rowBase + tid) * IN_DIM;

    float2 bias[4];
#pragma unroll
    for (int j = 0; j < 4; ++j) bias[j] = *(const float2*)(g_bias + j * 8 + tig * 2);

    float acc[2][4][4];
#pragma unroll
    for (int t = 0; t < 2; ++t)
#pragma unroll
        for (int j = 0; j < 4; ++j)
#pragma unroll
            for (int r = 0; r < 4; ++r) acc[t][j][r] = 0.0f;

    // ---- prologue: start W(0) copy, then features(0) -> A tile ----
#pragma unroll
    for (int k = 0; k < 5; ++k) {
        int idx = tid + k * 128;                     // 560 x 16B
        if (idx < WCH / 16) cp16(w_b + (uint32_t)idx * 16, g_W + idx * 16);
    }
    CP_COMMIT();

    {
        float4 xv = *(const float4*)(xrow);          // inputs 0-3
        const float xin[4] = {xv.x, xv.y, xv.z, xv.w};
#pragma unroll
        for (int p = 0; p < 2; ++p) {
            uint32_t w[28];
            feat_words(xin[2 * p],     w);
            feat_words(xin[2 * p + 1], w + 14);
            uint4* dst = (uint4*)(sm + OFF_A + tid * ROWPAD + p * 112);
#pragma unroll
            for (int i = 0; i < 7; ++i)
                dst[i] = make_uint4(w[4 * i], w[4 * i + 1], w[4 * i + 2], w[4 * i + 3]);
        }
    }

#pragma unroll 1
    for (int c = 0; c < NCHUNK; ++c) {
        CP_WAIT0();                                  // this thread's W(c) slices done
        __syncthreads();                             // A(c) + everyone's W(c) visible

        // issue W(c+1) into the other ring slot (disjoint from W(c) being read)
        if (c + 1 < NCHUNK) {
            const uint8_t* src = g_W + (size_t)(c + 1) * WCH;
            uint32_t dst = w_b + (uint32_t)((c + 1) & 1) * WCH;
#pragma unroll
            for (int k = 0; k < 5; ++k) {
                int idx = tid + k * 128;
                if (idx < WCH / 16) cp16(dst + (uint32_t)idx * 16, src + idx * 16);
            }
        }
        CP_COMMIT();

        // prefetch next chunk's x early (long latency tolerated)
        float4 xv;
        if (c + 1 < NCHUNK) xv = *(const float4*)(xrow + (c + 1) * 4);

        // ---- MMA(c) ----
        const uint32_t wbuf = w_b + (uint32_t)(c & 1) * WCH;
        const uint32_t aW = a_b + (uint32_t)(wid * 32) * ROWPAD;
#pragma unroll
        for (int s = 0; s < KSTEPS; ++s) {
            uint32_t a0[4], a1[4], b01[4], b23[4];
            uint32_t arow = aW + (uint32_t)(lane & 15) * ROWPAD + s * 32 + (lane >> 4) * 16;
            ldsm4(a0, arow);
            ldsm4(a1, arow + 16 * ROWPAD);
            uint32_t brow = wbuf + (uint32_t)(16 * s + (lane & 15)) * 80 + (lane >> 4) * 16;
            ldsm4t(b01, brow);                       // n-tiles 0,1
            ldsm4t(b23, brow + 32);                  // n-tiles 2,3
            mma16816(acc[0][0], a0, b01 + 0); mma16816(acc[0][1], a0, b01 + 2);
            mma16816(acc[0][2], a0, b23 + 0); mma16816(acc[0][3], a0, b23 + 2);
            mma16816(acc[1][0], a1, b01 + 0); mma16816(acc[1][1], a1, b01 + 2);
            mma16816(acc[1][2], a1, b23 + 0); mma16816(acc[1][3], a1, b23 + 2);
        }

        __syncthreads();                             // all ldsm reads of A(c) done

        // ---- features(c+1) -> A tile (overlaps HMMA drain) ----
        if (c + 1 < NCHUNK) {
            const float xin[4] = {xv.x, xv.y, xv.z, xv.w};
#pragma unroll
            for (int p = 0; p < 2; ++p) {
                uint32_t w[28];
                feat_words(xin[2 * p],     w);
                feat_words(xin[2 * p + 1], w + 14);
                uint4* dst = (uint4*)(sm + OFF_A + tid * ROWPAD + p * 112);
#pragma unroll
                for (int i = 0; i < 7; ++i)
                    dst[i] = make_uint4(w[4 * i], w[4 * i + 1], w[4 * i + 2], w[4 * i + 3]);
            }
        }
    }

    // epilogue: bias + store (D frag: d0,d1 -> row g; d2,d3 -> row g+8)
#pragma unroll
    for (int t = 0; t < 2; ++t) {
        int r0 = rowBase + wid * 32 + t * 16 + g;
#pragma unroll
        for (int j = 0; j < 4; ++j) {
            float2 v0 = make_float2(acc[t][j][0] + bias[j].x, acc[t][j][1] + bias[j].y);
            float2 v1 = make_float2(acc[t][j][2] + bias[j].x, acc[t][j][3] + bias[j].y);
            *(float2*)(out + (size_t)r0 * OUT_DIM + j * 8 + tig * 2)       = v0;
            *(float2*)(out + (size_t)(r0 + 8) * OUT_DIM + j * 8 + tig * 2) = v1;
        }
    }
}

// ---------------- launch ----------------
extern "C" void kernel_launch(void* const* d_in, const int* in_sizes, int n_in,
                              void* d_out, int out_size) {
    (void)in_sizes; (void)n_in; (void)out_size;
    const float* x     = (const float*)d_in[0];
    const float* coeff = (const float*)d_in[1];
    const float* bw    = (const float*)d_in[2];
    const float* bb    = (const float*)d_in[3];
    const float* ew    = (const float*)d_in[4];
    float* out = (float*)d_out;

    cudaFuncSetAttribute(kan_main, cudaFuncAttributeMaxDynamicSharedMemorySize, SMEM_TOTAL);

    kan_prep<<<16, 256>>>(coeff, bw, bb, ew);
    kan_main<<<NCTA, TPB, SMEM_TOTAL>>>(x, out);
}

// round 10
// speedup vs baseline: 11.5443x; 1.8484x over previous
#include <cuda_runtime.h>
#include <cuda_fp16.h>
#include <cstdint>

#define IN_DIM   128
#define OUT_DIM  32
#define NCHUNK   8             // 16 inputs per chunk
#define CH_IN    16
#define KSTEPS   9             // 16*9/16
#define WCH      11520         // W chunk: 144 k-rows * 80B (64B data + 16B pad)
#define WIMG     92160         // 1152 rows * 80B
#define ROWPAD   304           // A tile row pitch: 288B data + 16B pad (conflict-free)
#define TPB      128
#define NCTA     1024          // 131072 rows / 128

// smem layout (bytes): A tile then W ring
#define OFF_A    0             // 128 * 304 = 38912
#define OFF_W    38912         // 2 * 11520 = 23040
#define SMEM_TOTAL 61952

// spline constants: centers start -5/11, step 2/11, spacing 0.4+1e-6
#define KAN_C0   (-5.0f / 11.0f)
#define KAN_IS   (1.0f / (0.4f + 1e-6f))
#define KAN_D1   ((2.0f / 11.0f) * KAN_IS)

__device__ __align__(16) uint8_t g_W[WIMG];     // pre-folded fp16 B image, 80B pitch
__device__ __align__(16) float   g_bias[OUT_DIM];

// ---------------- helpers ----------------
__device__ __forceinline__ uint32_t smem_u32(const void* p) {
    uint32_t a;
    asm("{ .reg .u64 t; cvta.to.shared.u64 t, %1; cvt.u32.u64 %0, t; }" : "=r"(a) : "l"(p));
    return a;
}
__device__ __forceinline__ void cp16(uint32_t sdst, const void* gsrc) {
    asm volatile("cp.async.ca.shared.global [%0], [%1], 16;"
        :: "r"(sdst), "l"(__cvta_generic_to_global(gsrc)));
}
#define CP_COMMIT() asm volatile("cp.async.commit_group;" ::: "memory")
#define CP_WAIT0()  asm volatile("cp.async.wait_group 0;" ::: "memory")

__device__ __forceinline__ void ldsm4(uint32_t* r, uint32_t a) {
    asm volatile("ldmatrix.sync.aligned.m8n8.x4.shared.b16 {%0,%1,%2,%3}, [%4];"
        : "=r"(r[0]), "=r"(r[1]), "=r"(r[2]), "=r"(r[3]) : "r"(a));
}
__device__ __forceinline__ void ldsm4t(uint32_t* r, uint32_t a) {
    asm volatile("ldmatrix.sync.aligned.m8n8.x4.trans.shared.b16 {%0,%1,%2,%3}, [%4];"
        : "=r"(r[0]), "=r"(r[1]), "=r"(r[2]), "=r"(r[3]) : "r"(a));
}
__device__ __forceinline__ void mma16816(float* d, const uint32_t* a, const uint32_t* b) {
    asm volatile("mma.sync.aligned.m16n8k16.row.col.f32.f16.f16.f32 "
        "{%0,%1,%2,%3}, {%4,%5,%6,%7}, {%8,%9}, {%0,%1,%2,%3};"
        : "+f"(d[0]), "+f"(d[1]), "+f"(d[2]), "+f"(d[3])
        : "r"(a[0]), "r"(a[1]), "r"(a[2]), "r"(a[3]), "r"(b[0]), "r"(b[1]));
}
__device__ __forceinline__ uint32_t pkhf(float lo, float hi) {   // low half = lo
    uint32_t r;
    asm("cvt.rn.f16x2.f32 %0, %1, %2;" : "=r"(r) : "f"(hi), "f"(lo));
    return r;
}

// ---------------- prep: fold weights to fp16, 80B-pitch rows ----------------
// B row (global k = i*9 + f) holds W[k][j] = ew[i][j] * {base_weight | coeff[f-1]}
__global__ void kan_prep(const float* __restrict__ coeff, const float* __restrict__ bw,
                         const float* __restrict__ bb, const float* __restrict__ ew) {
    int t = blockIdx.x * 256 + threadIdx.x;
    if (t < IN_DIM * OUT_DIM) {
        int i = t >> 5, j = t & 31;
        float e = ew[t];
        float w[9];
        w[0] = e * bw[t];
#pragma unroll
        for (int k = 0; k < 8; ++k) w[1 + k] = e * coeff[t * 8 + k];
        uint8_t* base = g_W + (size_t)(i * 9) * 80 + j * 2;
#pragma unroll
        for (int f = 0; f < 9; ++f)
            *(__half*)(base + f * 80) = __float2half_rn(w[f]);
    }
    if (blockIdx.x == 0 && threadIdx.x < OUT_DIM) {
        int j = threadIdx.x;
        float s = 0.0f;
        for (int i = 0; i < IN_DIM; ++i) s += ew[i * OUT_DIM + j] * bb[i * OUT_DIM + j];
        g_bias[j] = s;
    }
}

// ---------------- main ----------------
extern __shared__ uint8_t sm[];

__device__ __forceinline__ void feats(float xq, float* f) {
    const float QC = __expf(-KAN_D1 * KAN_D1);
    const float MB = -0.5f * KAN_D1 * KAN_D1;
    float e = __expf(-xq);
    f[0] = __fdividef(xq, 1.0f + e);                 // silu
    float z0 = (xq - KAN_C0) * KAN_IS;
    float b = __expf(-0.5f * z0 * z0);
    float m = __expf(fmaf(z0, KAN_D1, MB));
    f[1] = b;
#pragma unroll
    for (int k = 2; k <= 8; ++k) { b *= m; m *= QC; f[k] = b; }
}

// one group: 8 inputs -> 72 fp16 slots -> 36 words -> 9 uint4 STS
__device__ __forceinline__ void feat_group(const float* xq, uint8_t* dst) {
    uint32_t w[36];
    float carry = 0.0f;
#pragma unroll
    for (int q = 0; q < 8; ++q) {
        float f[9];
        feats(xq[q], f);
#pragma unroll
        for (int t = 0; t < 9; ++t) {
            int idx = 9 * q + t;
            if (idx & 1) w[idx >> 1] = pkhf(carry, f[t]);
            else         carry = f[t];
        }
    }
    uint4* d4 = (uint4*)dst;
#pragma unroll
    for (int i = 0; i < 9; ++i)
        d4[i] = make_uint4(w[4 * i], w[4 * i + 1], w[4 * i + 2], w[4 * i + 3]);
}

__global__ __launch_bounds__(TPB, 3)
void kan_main(const float* __restrict__ x, float* __restrict__ out) {
    const int tid  = threadIdx.x;
    const int wid  = tid >> 5;
    const int lane = tid & 31;
    const int g    = lane >> 2;
    const int tig  = lane & 3;
    const uint32_t sb  = smem_u32(sm);
    const uint32_t a_b = sb + OFF_A, w_b = sb + OFF_W;

    const int rowBase = blockIdx.x * TPB;
    const float* __restrict__ xrow = x + (size_t)(rowBase + tid) * IN_DIM;

    float2 bias[4];
#pragma unroll
    for (int j = 0; j < 4; ++j) bias[j] = *(const float2*)(g_bias + j * 8 + tig * 2);

    float acc[2][4][4];
#pragma unroll
    for (int t = 0; t < 2; ++t)
#pragma unroll
        for (int j = 0; j < 4; ++j)
#pragma unroll
            for (int r = 0; r < 4; ++r) acc[t][j][r] = 0.0f;

    // ---- prologue: start W(0) copy, then features(0) -> A tile ----
#pragma unroll
    for (int k = 0; k < 6; ++k) {
        int idx = tid + k * 128;                     // 720 x 16B
        if (idx < WCH / 16) cp16(w_b + (uint32_t)idx * 16, g_W + idx * 16);
    }
    CP_COMMIT();

    {
        float xq[8];
#pragma unroll
        for (int p = 0; p < 2; ++p) {
            *(float4*)(xq)     = *(const float4*)(xrow + p * 8);
            *(float4*)(xq + 4) = *(const float4*)(xrow + p * 8 + 4);
            feat_group(xq, sm + OFF_A + tid * ROWPAD + p * 144);
        }
    }

#pragma unroll 1
    for (int c = 0; c < NCHUNK; ++c) {
        CP_WAIT0();                                  // this thread's W(c) slices done
        __syncthreads();                             // A(c) + everyone's W(c) visible

        // distance-1 prefetch: W(c+1) into the other ring slot
        if (c + 1 < NCHUNK) {
            const uint8_t* src = g_W + (size_t)(c + 1) * WCH;
            uint32_t dst = w_b + (uint32_t)((c + 1) & 1) * WCH;
#pragma unroll
            for (int k = 0; k < 6; ++k) {
                int idx = tid + k * 128;
                if (idx < WCH / 16) cp16(dst + (uint32_t)idx * 16, src + idx * 16);
            }
        }
        CP_COMMIT();

        // ---- MMA(c) ----
        const uint32_t wbuf = w_b + (uint32_t)(c & 1) * WCH;
        const uint32_t aW = a_b + (uint32_t)(wid * 32) * ROWPAD;
#pragma unroll
        for (int s = 0; s < KSTEPS; ++s) {
            uint32_t a0[4], a1[4], b01[4], b23[4];
            uint32_t arow = aW + (uint32_t)(lane & 15) * ROWPAD + s * 32 + (lane >> 4) * 16;
            ldsm4(a0, arow);
            ldsm4(a1, arow + 16 * ROWPAD);
            uint32_t brow = wbuf + (uint32_t)(16 * s + (lane & 15)) * 80 + (lane >> 4) * 16;
            ldsm4t(b01, brow);                       // n 0..15
            ldsm4t(b23, brow + 32);                  // n 16..31
            mma16816(acc[0][0], a0, b01 + 0); mma16816(acc[0][1], a0, b01 + 2);
            mma16816(acc[0][2], a0, b23 + 0); mma16816(acc[0][3], a0, b23 + 2);
            mma16816(acc[1][0], a1, b01 + 0); mma16816(acc[1][1], a1, b01 + 2);
            mma16816(acc[1][2], a1, b23 + 0); mma16816(acc[1][3], a1, b23 + 2);
        }

        __syncthreads();                             // all ldsm reads of A(c) done

        // ---- features(c+1) -> A tile (overlaps HMMA drain) ----
        if (c + 1 < NCHUNK) {
            float xq[8];
#pragma unroll
            for (int p = 0; p < 2; ++p) {
                const float* xs = xrow + (c + 1) * CH_IN + p * 8;
                *(float4*)(xq)     = *(const float4*)(xs);
                *(float4*)(xq + 4) = *(const float4*)(xs + 4);
                feat_group(xq, sm + OFF_A + tid * ROWPAD + p * 144);
            }
        }
    }

    // epilogue: bias + store (D frag: d0,d1 -> row g; d2,d3 -> row g+8)
#pragma unroll
    for (int t = 0; t < 2; ++t) {
        int r0 = rowBase + wid * 32 + t * 16 + g;
#pragma unroll
        for (int j = 0; j < 4; ++j) {
            float2 v0 = make_float2(acc[t][j][0] + bias[j].x, acc[t][j][1] + bias[j].y);
            float2 v1 = make_float2(acc[t][j][2] + bias[j].x, acc[t][j][3] + bias[j].y);
            *(float2*)(out + (size_t)r0 * OUT_DIM + j * 8 + tig * 2)       = v0;
            *(float2*)(out + (size_t)(r0 + 8) * OUT_DIM + j * 8 + tig * 2) = v1;
        }
    }
}

// ---------------- launch ----------------
extern "C" void kernel_launch(void* const* d_in, const int* in_sizes, int n_in,
                              void* d_out, int out_size) {
    (void)in_sizes; (void)n_in; (void)out_size;
    const float* x     = (const float*)d_in[0];
    const float* coeff = (const float*)d_in[1];
    const float* bw    = (const float*)d_in[2];
    const float* bb    = (const float*)d_in[3];
    const float* ew    = (const float*)d_in[4];
    float* out = (float*)d_out;

    cudaFuncSetAttribute(kan_main, cudaFuncAttributeMaxDynamicSharedMemorySize, SMEM_TOTAL);

    kan_prep<<<16, 256>>>(coeff, bw, bb, ew);
    kan_main<<<NCTA, TPB, SMEM_TOTAL>>>(x, out);
}

// round 11
// speedup vs baseline: 13.0589x; 1.1312x over previous
#include <cuda_runtime.h>
#include <cuda_fp16.h>
#include <cstdint>

#define IN_DIM   128
#define OUT_DIM  32
#define NCHUNK   8             // 16 inputs per chunk
#define CH_IN    16
#define KSTEPS   9             // per chunk
#define KS_TOT   72            // 1152 / 16
#define ROWPAD   304           // A tile row pitch: 288B data + 16B pad (conflict-free, 16*odd)
#define TPB      128
#define NCTA     1024          // 131072 rows / 128

// spline constants: centers start -5/11, step 2/11, spacing 0.4+1e-6
#define KAN_C0   (-5.0f / 11.0f)
#define KAN_IS   (1.0f / (0.4f + 1e-6f))
#define KAN_D1   ((2.0f / 11.0f) * KAN_IS)

// B in fragment order: [kstep][half][lane] -> 16B ( = 4 regs )
__device__ __align__(16) uint4 g_Wf[KS_TOT * 2 * 32];
__device__ __align__(16) float g_bias[OUT_DIM];

// ---------------- helpers ----------------
__device__ __forceinline__ void ldsm4(uint32_t* r, uint32_t a) {
    asm volatile("ldmatrix.sync.aligned.m8n8.x4.shared.b16 {%0,%1,%2,%3}, [%4];"
        : "=r"(r[0]), "=r"(r[1]), "=r"(r[2]), "=r"(r[3]) : "r"(a));
}
__device__ __forceinline__ void mma16816(float* d, const uint32_t* a, const uint32_t* b) {
    asm volatile("mma.sync.aligned.m16n8k16.row.col.f32.f16.f16.f32 "
        "{%0,%1,%2,%3}, {%4,%5,%6,%7}, {%8,%9}, {%0,%1,%2,%3};"
        : "+f"(d[0]), "+f"(d[1]), "+f"(d[2]), "+f"(d[3])
        : "r"(a[0]), "r"(a[1]), "r"(a[2]), "r"(a[3]), "r"(b[0]), "r"(b[1]));
}
__device__ __forceinline__ uint32_t pkhf(float lo, float hi) {   // low half = lo
    uint32_t r;
    asm("cvt.rn.f16x2.f32 %0, %1, %2;" : "=r"(r) : "f"(hi), "f"(lo));
    return r;
}

// ---------------- prep: fold W and emit ldmatrix-equivalent fragments ----------------
// W[k][j] = ew[i][j] * (f==0 ? base_weight[i][j] : coeff[i][j][f-1]),  i=k/9, f=k%9
__device__ __forceinline__ float foldW(int k, int j, const float* coeff,
                                       const float* bw, const float* ew) {
    int i = k / 9, f = k - 9 * i;
    int t = i * OUT_DIM + j;
    float e = ew[t];
    return f == 0 ? e * bw[t] : e * coeff[t * 8 + (f - 1)];
}

__global__ void kan_prep(const float* __restrict__ coeff, const float* __restrict__ bw,
                         const float* __restrict__ bb, const float* __restrict__ ew) {
    int t = blockIdx.x * 256 + threadIdx.x;
    if (t < KS_TOT * 32) {
        int s = t >> 5, l = t & 31;
        uint32_t regs[8];
#pragma unroll
        for (int r = 0; r < 8; ++r) {
            // reg r (ldmatrix.x4.trans equivalent): n-tile r>>1, b-half r&1
            int n  = (r >> 1) * 8 + (l >> 2);
            int kk = 16 * s + 2 * (l & 3) + 8 * (r & 1);
            float lo = foldW(kk,     n, coeff, bw, ew);
            float hi = foldW(kk + 1, n, coeff, bw, ew);
            regs[r] = pkhf(lo, hi);
        }
        g_Wf[(s * 2 + 0) * 32 + l] = make_uint4(regs[0], regs[1], regs[2], regs[3]); // b01
        g_Wf[(s * 2 + 1) * 32 + l] = make_uint4(regs[4], regs[5], regs[6], regs[7]); // b23
    }
    if (blockIdx.x == 0 && threadIdx.x < OUT_DIM) {
        int j = threadIdx.x;
        float s = 0.0f;
        for (int i = 0; i < IN_DIM; ++i) s += ew[i * OUT_DIM + j] * bb[i * OUT_DIM + j];
        g_bias[j] = s;
    }
}

// ---------------- feature math ----------------
__device__ __forceinline__ void feats(float xq, float* f) {
    const float QC = __expf(-KAN_D1 * KAN_D1);
    const float MB = -0.5f * KAN_D1 * KAN_D1;
    float e = __expf(-xq);
    f[0] = __fdividef(xq, 1.0f + e);                 // silu
    float z0 = (xq - KAN_C0) * KAN_IS;
    float b = __expf(-0.5f * z0 * z0);
    float m = __expf(fmaf(z0, KAN_D1, MB));
    f[1] = b;
#pragma unroll
    for (int k = 2; k <= 8; ++k) { b *= m; m *= QC; f[k] = b; }
}

// one group: 8 inputs -> 72 fp16 slots -> 36 words -> 9 uint4 STS
__device__ __forceinline__ void feat_group(const float* xq, uint8_t* dst) {
    uint32_t w[36];
    float carry = 0.0f;
#pragma unroll
    for (int q = 0; q < 8; ++q) {
        float f[9];
        feats(xq[q], f);
#pragma unroll
        for (int t = 0; t < 9; ++t) {
            int idx = 9 * q + t;
            if (idx & 1) w[idx >> 1] = pkhf(carry, f[t]);
            else         carry = f[t];
        }
    }
    uint4* d4 = (uint4*)dst;
#pragma unroll
    for (int i = 0; i < 9; ++i)
        d4[i] = make_uint4(w[4 * i], w[4 * i + 1], w[4 * i + 2], w[4 * i + 3]);
}

// ---------------- main ----------------
__global__ __launch_bounds__(TPB, 4)
void kan_main(const float* __restrict__ x, float* __restrict__ out) {
    __shared__ __align__(16) uint8_t smA[TPB * ROWPAD];   // 38,912 B

    const int tid  = threadIdx.x;
    const int wid  = tid >> 5;
    const int lane = tid & 31;
    const int g    = lane >> 2;
    const int tig  = lane & 3;

    uint32_t a_b;
    asm("{ .reg .u64 t; cvta.to.shared.u64 t, %1; cvt.u32.u64 %0, t; }"
        : "=r"(a_b) : "l"((const void*)smA));

    const int rowBase = blockIdx.x * TPB;
    const float* __restrict__ xrow = x + (size_t)(rowBase + tid) * IN_DIM;

    float2 bias[4];
#pragma unroll
    for (int j = 0; j < 4; ++j) bias[j] = *(const float2*)(g_bias + j * 8 + tig * 2);

    float acc[2][4][4];
#pragma unroll
    for (int t = 0; t < 2; ++t)
#pragma unroll
        for (int j = 0; j < 4; ++j)
#pragma unroll
            for (int r = 0; r < 4; ++r) acc[t][j][r] = 0.0f;

    // ---- prologue: features(0) -> A tile ----
    {
        float xq[8];
#pragma unroll
        for (int p = 0; p < 2; ++p) {
            *(float4*)(xq)     = *(const float4*)(xrow + p * 8);
            *(float4*)(xq + 4) = *(const float4*)(xrow + p * 8 + 4);
            feat_group(xq, smA + tid * ROWPAD + p * 144);
        }
    }

#pragma unroll 1
    for (int c = 0; c < NCHUNK; ++c) {
        __syncthreads();                             // A(c) visible to all warps

        // prefetch next chunk's x early (long latency tolerated)
        float xq[8];
        if (c + 1 < NCHUNK) {
            *(float4*)(xq)     = *(const float4*)(xrow + (c + 1) * CH_IN);
            *(float4*)(xq + 4) = *(const float4*)(xrow + (c + 1) * CH_IN + 4);
        }

        // ---- MMA(c): B frags via LDG (L1/L2-hot), A via ldmatrix ----
        const uint4* __restrict__ wf = g_Wf + (size_t)(c * KSTEPS) * 64 + lane;
        const uint32_t aW = a_b + (uint32_t)(wid * 32) * ROWPAD;
#pragma unroll
        for (int s = 0; s < KSTEPS; ++s) {
            uint4 v01 = __ldg(wf + s * 64);
            uint4 v23 = __ldg(wf + s * 64 + 32);
            uint32_t b01[4] = {v01.x, v01.y, v01.z, v01.w};
            uint32_t b23[4] = {v23.x, v23.y, v23.z, v23.w};
            uint32_t a0[4], a1[4];
            uint32_t arow = aW + (uint32_t)(lane & 15) * ROWPAD + s * 32 + (lane >> 4) * 16;
            ldsm4(a0, arow);
            ldsm4(a1, arow + 16 * ROWPAD);
            mma16816(acc[0][0], a0, b01 + 0); mma16816(acc[0][1], a0, b01 + 2);
            mma16816(acc[0][2], a0, b23 + 0); mma16816(acc[0][3], a0, b23 + 2);
            mma16816(acc[1][0], a1, b01 + 0); mma16816(acc[1][1], a1, b01 + 2);
            mma16816(acc[1][2], a1, b23 + 0); mma16816(acc[1][3], a1, b23 + 2);
        }

        __syncthreads();                             // all ldsm reads of A(c) done

        // ---- features(c+1) -> A tile (overlaps HMMA drain) ----
        if (c + 1 < NCHUNK) {
            feat_group(xq, smA + tid * ROWPAD);
            float xq2[8];
            *(float4*)(xq2)     = *(const float4*)(xrow + (c + 1) * CH_IN + 8);
            *(float4*)(xq2 + 4) = *(const float4*)(xrow + (c + 1) * CH_IN + 12);
            feat_group(xq2, smA + tid * ROWPAD + 144);
        }
    }

    // epilogue: bias + store (D frag: d0,d1 -> row g; d2,d3 -> row g+8)
#pragma unroll
    for (int t = 0; t < 2; ++t) {
        int r0 = rowBase + wid * 32 + t * 16 + g;
#pragma unroll
        for (int j = 0; j < 4; ++j) {
            float2 v0 = make_float2(acc[t][j][0] + bias[j].x, acc[t][j][1] + bias[j].y);
            float2 v1 = make_float2(acc[t][j][2] + bias[j].x, acc[t][j][3] + bias[j].y);
            *(float2*)(out + (size_t)r0 * OUT_DIM + j * 8 + tig * 2)       = v0;
            *(float2*)(out + (size_t)(r0 + 8) * OUT_DIM + j * 8 + tig * 2) = v1;
        }
    }
}

// ---------------- launch ----------------
extern "C" void kernel_launch(void* const* d_in, const int* in_sizes, int n_in,
                              void* d_out, int out_size) {
    (void)in_sizes; (void)n_in; (void)out_size;
    const float* x     = (const float*)d_in[0];
    const float* coeff = (const float*)d_in[1];
    const float* bw    = (const float*)d_in[2];
    const float* bb    = (const float*)d_in[3];
    const float* ew    = (const float*)d_in[4];
    float* out = (float*)d_out;

    kan_prep<<<9, 256>>>(coeff, bw, bb, ew);
    kan_main<<<NCTA, TPB>>>(x, out);
}